// round 8
// baseline (speedup 1.0000x reference)
#include <cuda_runtime.h>
#include <math.h>

#define BNH 32
#define LL  1024
#define DD  64
#define RR  129
#define TI  16
#define NT  256

#define PSTR 1028
#define KSTR 68
#define VSTR 72

// shared layout (float units), total 28816 floats = 112.56 KB -> 2 CTAs/SM
//   av_s [16][132] @ 0      qe in phases A/B, av afterwards
//   posi [16]      @ 2112
//   posa [1024]    @ 2128
//   p_s  [16][1028]@ 3152   emb_k (phase A) -> scores -> p(tf32)
//   G    [9216]    @ 19600  q (start) -> k-tiles[128][68] -> a64[16][264] -> v-tiles[128][72] -> emb_v
#define OFF_AV   0
#define OFF_POSI 2112
#define OFF_POSA 2128
#define OFF_P    3152
#define OFF_G    19600
#define SMEM_FLOATS 28816
#define SMEM_BYTES  (SMEM_FLOATS * 4)

#define FIX_SCALE 4503599627370496.0f   /* 2^52 */
#define FIX_INV   (1.0f / 4503599627370496.0f)

__device__ __forceinline__ unsigned tf32b(float x) {
    unsigned u;
    asm("cvt.rna.tf32.f32 %0, %1;" : "=r"(u) : "f"(x));
    return u;
}
__device__ __forceinline__ float tf32r(float x) { return __uint_as_float(tf32b(x)); }
__device__ __forceinline__ float4 tf32r4(float4 a) {
    a.x = tf32r(a.x); a.y = tf32r(a.y); a.z = tf32r(a.z); a.w = tf32r(a.w);
    return a;
}

#define MMA_TF32(c0,c1,c2,c3,a0,a1,a2,a3,b0,b1)                               \
    asm volatile("mma.sync.aligned.m16n8k8.row.col.f32.tf32.tf32.f32 "        \
                 "{%0,%1,%2,%3}, {%4,%5,%6,%7}, {%8,%9}, {%0,%1,%2,%3};"      \
                 : "+f"(c0), "+f"(c1), "+f"(c2), "+f"(c3)                      \
                 : "r"(a0), "r"(a1), "r"(a2), "r"(a3), "r"(b0), "r"(b1))

extern "C" __global__ void __launch_bounds__(NT, 2)
attn_rel_kernel(const float* __restrict__ gq, const float* __restrict__ gk,
                const float* __restrict__ gv, const float* __restrict__ gw,
                const float* __restrict__ gek, const float* __restrict__ gev,
                const int* __restrict__ gpos, const unsigned char* __restrict__ gmask,
                float* __restrict__ gout, float* __restrict__ gp)
{
    extern __shared__ float sm[];
    float* av_s = sm + OFF_AV;
    int*   posi = (int*)(sm + OFF_POSI);
    int*   posa = (int*)(sm + OFF_POSA);
    float* p_s  = sm + OFF_P;
    float* G    = sm + OFF_G;
    float* q_s  = G;        // q aliased into G until k tiles arrive
    float* ek_s = p_s;      // emb_k aliased into p_s during phase A

    const int b    = blockIdx.y;
    const int i0   = blockIdx.x * TI;
    const int tid  = threadIdx.x;
    const int lane = tid & 31;
    const int warp = tid >> 5;          // 0..7
    const unsigned FULL = 0xffffffffu;

    const int gid  = lane >> 2;         // 0..7
    const int tid4 = lane & 3;          // 0..3

    // ---------------- loads: q -> G, emb_k -> p_s, pos ----------------
    {
        const float4* q4 = (const float4*)(gq + ((size_t)b * LL + i0) * DD);
        int row = tid >> 4, c4 = tid & 15;
        *(float4*)(q_s + row * KSTR + c4 * 4) = q4[tid];
        if (tid < TI) posi[tid] = gpos[b * LL + i0 + tid];
        #pragma unroll
        for (int t = tid; t < LL; t += NT) posa[t] = gpos[b * LL + t];
        for (int e = tid; e < RR * DD; e += NT) {
            int r = e >> 6, d = e & 63;
            ek_s[r * 68 + d] = gek[e];
        }
    }
    __syncthreads();

    // ---------------- phase A: qe[i][r] = q[i] . emb_k[r]  (exact fp32) ----------------
    for (int e = tid; e < TI * RR; e += NT) {
        int i = e / RR, r = e - i * RR;
        const float4* qa = (const float4*)(q_s + i * KSTR);
        const float4* ea = (const float4*)(ek_s + r * 68);
        float acc = 0.f;
        #pragma unroll
        for (int c = 0; c < 16; c++) {
            float4 a = qa[c], e2 = ea[c];
            acc += a.x*e2.x + a.y*e2.y + a.z*e2.z + a.w*e2.w;
        }
        av_s[i * 132 + r] = acc;
    }

    // persistent tf32 A-fragments of q (from G before k tiles overwrite it)
    unsigned af[8][4];
    #pragma unroll
    for (int ks = 0; ks < 8; ks++) {
        af[ks][0] = tf32b(q_s[ gid      * KSTR + ks * 8 + tid4    ]);
        af[ks][1] = tf32b(q_s[(gid + 8) * KSTR + ks * 8 + tid4    ]);
        af[ks][2] = tf32b(q_s[ gid      * KSTR + ks * 8 + tid4 + 4]);
        af[ks][3] = tf32b(q_s[(gid + 8) * KSTR + ks * 8 + tid4 + 4]);
    }

    // ---------------- phase B: scores = (QK^T + qe[table] + attn_w)/8, mask ----------------
    const int jbase = warp * 16;        // 16 j columns per warp per 128-tile
    const int i_lo = gid, i_hi = gid + 8;
    const int pi_lo = posi[i_lo], pi_hi = posi[i_hi];
    const size_t row_lo = ((size_t)b * LL + (i0 + i_lo)) * LL;
    const size_t row_hi = ((size_t)b * LL + (i0 + i_hi)) * LL;

    for (int jt = 0; jt < 8; jt++) {
        __syncthreads();                // G free (q frags built / prev mma done)
        {   // k tile jt -> G (tf32, stride 68)
            const float4* k4 = (const float4*)(gk + ((size_t)b * LL + jt * 128) * DD);
            #pragma unroll
            for (int s = 0; s < 8; s++) {
                int f = tid + s * NT;
                int row = f >> 4, d4 = f & 15;
                *(float4*)(G + row * KSTR + d4 * 4) = tf32r4(k4[f]);
            }
        }
        // prefetch attn_w / mask for the epilogue (both n-tiles)
        const int jg0 = jt * 128 + jbase + tid4 * 2;
        float2 w_lo0 = *(const float2*)(gw + row_lo + jg0);
        float2 w_hi0 = *(const float2*)(gw + row_hi + jg0);
        float2 w_lo1 = *(const float2*)(gw + row_lo + jg0 + 8);
        float2 w_hi1 = *(const float2*)(gw + row_hi + jg0 + 8);
        uchar2 m_lo0 = *(const uchar2*)(gmask + row_lo + jg0);
        uchar2 m_hi0 = *(const uchar2*)(gmask + row_hi + jg0);
        uchar2 m_lo1 = *(const uchar2*)(gmask + row_lo + jg0 + 8);
        uchar2 m_hi1 = *(const uchar2*)(gmask + row_hi + jg0 + 8);
        __syncthreads();

        float c0[4] = {0.f, 0.f, 0.f, 0.f};
        float c1[4] = {0.f, 0.f, 0.f, 0.f};
        #pragma unroll
        for (int ks = 0; ks < 8; ks++) {
            const float* kb0 = G + (jbase + gid) * KSTR + ks * 8 + tid4;
            const float* kb1 = kb0 + 8 * KSTR;
            unsigned b00 = __float_as_uint(kb0[0]);
            unsigned b01 = __float_as_uint(kb0[4]);
            unsigned b10 = __float_as_uint(kb1[0]);
            unsigned b11 = __float_as_uint(kb1[4]);
            MMA_TF32(c0[0], c0[1], c0[2], c0[3],
                     af[ks][0], af[ks][1], af[ks][2], af[ks][3], b00, b01);
            MMA_TF32(c1[0], c1[1], c1[2], c1[3],
                     af[ks][0], af[ks][1], af[ks][2], af[ks][3], b10, b11);
        }

        // epilogue: rel-pos gather + attn_w, scale, mask, store to p_s
        #pragma unroll
        for (int t = 0; t < 2; t++) {
            float* cc = t ? c1 : c0;
            int jg = jg0 + t * 8;
            float2 wl = t ? w_lo1 : w_lo0;
            float2 wh = t ? w_hi1 : w_hi0;
            uchar2 ml = t ? m_lo1 : m_lo0;
            uchar2 mh = t ? m_hi1 : m_hi0;
            int pj0 = posa[jg], pj1 = posa[jg + 1];
            int d00 = max(-64, min(64, pj0 - pi_lo)) + 64;
            int d01 = max(-64, min(64, pj1 - pi_lo)) + 64;
            int d10 = max(-64, min(64, pj0 - pi_hi)) + 64;
            int d11 = max(-64, min(64, pj1 - pi_hi)) + 64;
            float s00 = (cc[0] + av_s[i_lo * 132 + d00] + wl.x) * 0.125f;
            float s01 = (cc[1] + av_s[i_lo * 132 + d01] + wl.y) * 0.125f;
            float s10 = (cc[2] + av_s[i_hi * 132 + d10] + wh.x) * 0.125f;
            float s11 = (cc[3] + av_s[i_hi * 132 + d11] + wh.y) * 0.125f;
            if (ml.x) s00 = -INFINITY;
            if (ml.y) s01 = -INFINITY;
            if (mh.x) s10 = -INFINITY;
            if (mh.y) s11 = -INFINITY;
            *(float2*)(p_s + i_lo * PSTR + jg) = make_float2(s00, s01);
            *(float2*)(p_s + i_hi * PSTR + jg) = make_float2(s10, s11);
        }
    }
    __syncthreads();

    // ---------------- phase C: softmax + p write + av scatter (register-resident) ----------------
    #pragma unroll
    for (int ii = 0; ii < 2; ii++) {
        const int i = warp * 2 + ii;
        float* row = p_s + i * PSTR;
        float r[32];
        #pragma unroll
        for (int c = 0; c < 32; c++) r[c] = row[lane + 32*c];

        float m = -INFINITY;
        #pragma unroll
        for (int c = 0; c < 32; c++) m = fmaxf(m, r[c]);
        #pragma unroll
        for (int o = 16; o > 0; o >>= 1) m = fmaxf(m, __shfl_xor_sync(FULL, m, o));

        float sum = 0.f;
        #pragma unroll
        for (int c = 0; c < 32; c++) {
            r[c] = __expf(r[c] - m);
            sum += r[c];
        }
        #pragma unroll
        for (int o = 16; o > 0; o >>= 1) sum += __shfl_xor_sync(FULL, sum, o);
        float inv = 1.0f / sum;

        // fixed-point scatter region (2 banks per bucket; exact -> deterministic)
        unsigned long long* a64 = (unsigned long long*)(sm + OFF_G) + (size_t)i * 264;
        for (int idx = lane; idx < 264; idx += 32) a64[idx] = 0ull;
        __syncwarp();

        const int pi = posi[i];
        const int bank = lane & 1;
        const size_t prow = ((size_t)b * LL + (i0 + i)) * LL;
        #pragma unroll
        for (int c = 0; c < 32; c++) {
            int j = lane + 32*c;
            float pv = r[c] * inv;
            if (gp) gp[prow + j] = pv;
            int diff = posa[j] - pi;
            diff = max(-64, min(64, diff));
            atomicAdd(a64 + (diff + 64) * 2 + bank,
                      (unsigned long long)(pv * FIX_SCALE));
            row[j] = tf32r(pv);         // tf32 p for the P@V mma (gp holds exact p)
        }
        __syncwarp();

        #pragma unroll
        for (int c = 0; c < 5; c++) {
            int idx = lane + 32*c;
            if (idx < RR)
                av_s[i * 132 + idx] =
                    __ull2float_rn(a64[idx*2] + a64[idx*2+1]) * FIX_INV;
        }
    }
    __syncthreads();

    // ---------------- phase D: out = P @ V  (tf32 mma) ----------------
    const int ntile = warp;             // d-block of 8
    float cd0 = 0.f, cd1 = 0.f, cd2 = 0.f, cd3 = 0.f;

    for (int jt = 0; jt < 8; jt++) {
        {   // v tile jt -> G (tf32, stride 72)
            const float4* v4 = (const float4*)(gv + ((size_t)b * LL + jt * 128) * DD);
            #pragma unroll
            for (int s = 0; s < 8; s++) {
                int f = tid + s * NT;
                int row = f >> 4, d4 = f & 15;
                *(float4*)(G + row * VSTR + d4 * 4) = tf32r4(v4[f]);
            }
        }
        __syncthreads();

        #pragma unroll
        for (int ks = 0; ks < 16; ks++) {
            int jrow = ks * 8;
            int jcol = jt * 128 + jrow + tid4;
            unsigned a0 = __float_as_uint(p_s[ gid      * PSTR + jcol    ]);
            unsigned a1 = __float_as_uint(p_s[(gid + 8) * PSTR + jcol    ]);
            unsigned a2 = __float_as_uint(p_s[ gid      * PSTR + jcol + 4]);
            unsigned a3 = __float_as_uint(p_s[(gid + 8) * PSTR + jcol + 4]);
            const float* vb = G + (jrow + tid4) * VSTR + ntile * 8 + gid;
            unsigned b0 = __float_as_uint(vb[0]);
            unsigned b1 = __float_as_uint(vb[4 * VSTR]);
            MMA_TF32(cd0, cd1, cd2, cd3, a0, a1, a2, a3, b0, b1);
        }
        __syncthreads();                // mma done before next STS / emb_v load
    }

    // load emb_v -> G (free now)
    for (int e = tid; e < RR * DD; e += NT) {
        int r = e >> 6, d = e & 63;
        G[r * 68 + d] = gev[e];
    }
    __syncthreads();

    // ---------------- final: out = PV-frag + av @ emb_v ----------------
    if (gout) {
        const int d0 = ntile * 8 + tid4 * 2;
        const float* av_lo = av_s + i_lo * 132;
        const float* av_hi = av_s + i_hi * 132;
        float s00 = 0.f, s01 = 0.f, s10 = 0.f, s11 = 0.f;
        #pragma unroll 8
        for (int r = 0; r < RR; r++) {
            float a_lo = av_lo[r], a_hi = av_hi[r];
            float2 ev2 = *(const float2*)(G + r * 68 + d0);
            s00 += a_lo * ev2.x; s01 += a_lo * ev2.y;
            s10 += a_hi * ev2.x; s11 += a_hi * ev2.y;
        }
        *(float2*)(gout + ((size_t)b * LL + i0 + i_lo) * DD + d0) =
            make_float2(cd0 + s00, cd1 + s01);
        *(float2*)(gout + ((size_t)b * LL + i0 + i_hi) * DD + d0) =
            make_float2(cd2 + s10, cd3 + s11);
    }
}

extern "C" void kernel_launch(void* const* d_in, const int* in_sizes, int n_in,
                              void* d_out, int out_size)
{
    const float* q   = (const float*)d_in[0];
    const float* k   = (const float*)d_in[1];
    const float* v   = (const float*)d_in[2];
    const float* w   = (const float*)d_in[3];
    const float* ek  = (const float*)d_in[4];
    const float* ev  = (const float*)d_in[5];
    const int*   pos = (const int*)d_in[6];
    const unsigned char* mask = (const unsigned char*)d_in[7];

    const long OUT_N = (long)BNH * LL * DD;   // 2,097,152
    const long P_N   = (long)BNH * LL * LL;   // 33,554,432

    float* outp = nullptr;
    float* pp   = nullptr;
    if ((long)out_size == OUT_N) {
        outp = (float*)d_out;
    } else if ((long)out_size == P_N) {
        pp = (float*)d_out;
    } else {
        outp = (float*)d_out;
        pp   = (float*)d_out + OUT_N;
    }

    cudaFuncSetAttribute(attn_rel_kernel,
                         cudaFuncAttributeMaxDynamicSharedMemorySize, SMEM_BYTES);
    dim3 grid(LL / TI, BNH);
    attn_rel_kernel<<<grid, NT, SMEM_BYTES>>>(q, k, v, w, ek, ev, pos, mask, outp, pp);
}